// round 16
// baseline (speedup 1.0000x reference)
#include <cuda_runtime.h>
#include <cuda_bf16.h>
#include <cuda_fp16.h>
#include <cstdint>
#include <cstddef>

#define HD   128
#define NMAX 100000
#define GMAX 1024
#define ELLW 64

// ---------------- scratch (device globals; no allocation allowed) ----------
__device__ __align__(256) __half g_msg[NMAX * HD];            // m' fp16 = (h @ W) * dinv[row]
__device__ __align__(256) __nv_bfloat16 g_h[NMAX * HD];       // h bf16 (GEMM A input)
__device__ __align__(256) __nv_bfloat16 g_whi[4 * HD * HD];   // W^T split hi ([N,K] row-major)
__device__ __align__(256) __nv_bfloat16 g_wlo[4 * HD * HD];   // W^T split lo
__device__ __align__(256) int   g_ell[NMAX * ELLW];
__device__ __align__(256) int   g_cnt[NMAX];
__device__ __align__(256) float g_pooled[GMAX * HD];
__device__ __align__(256) float g_counts[GMAX];

// ---------------- helpers ----------------------------------------------------
__device__ __forceinline__ uint32_t smem_u32(const void* p) {
    uint32_t a;
    asm("{ .reg .u64 t; cvta.to.shared.u64 t, %1; cvt.u32.u64 %0, t; }" : "=r"(a) : "l"(p));
    return a;
}

__device__ __forceinline__ void ldm4(uint32_t* r, uint32_t addr) {
    asm volatile("ldmatrix.sync.aligned.m8n8.x4.shared.b16 {%0,%1,%2,%3}, [%4];"
                 : "=r"(r[0]), "=r"(r[1]), "=r"(r[2]), "=r"(r[3]) : "r"(addr));
}

__device__ __forceinline__ void mma_bf16(float* c, const uint32_t* a,
                                         uint32_t b0, uint32_t b1) {
    asm volatile(
        "mma.sync.aligned.m16n8k16.row.col.f32.bf16.bf16.f32 "
        "{%0,%1,%2,%3}, {%4,%5,%6,%7}, {%8,%9}, {%0,%1,%2,%3};"
        : "+f"(c[0]), "+f"(c[1]), "+f"(c[2]), "+f"(c[3])
        : "r"(a[0]), "r"(a[1]), "r"(a[2]), "r"(a[3]), "r"(b0), "r"(b1));
}

__device__ __forceinline__ uint32_t pack_bf16x2(float x, float y) {
    __nv_bfloat162 b = {__float2bfloat16(x), __float2bfloat16(y)};
    return *(uint32_t*)&b;
}

// SMEM plan: padded rows, stride 136 bf16 = 272 bytes (conflict-free ldmatrix)
#define ROWB 272
#define SA    0
#define SW_HI (SA + 64 * ROWB)
#define SW_LO (SW_HI + 128 * ROWB)
#define S_TOT (SW_LO + 128 * ROWB)

#define GEMM_CTAS 296   // 2 per SM, persistent

// ---------------- persistent HMMA GEMM (2-pass bf16) [exact R12] -------------
__global__ __launch_bounds__(256, 2) void gemm_hmma(
    const __nv_bfloat16* __restrict__ A, const float* __restrict__ xf,
    const __nv_bfloat16* __restrict__ Whi, const __nv_bfloat16* __restrict__ Wlo,
    const int* __restrict__ cnt, __half* __restrict__ M, int n, int ntiles)
{
    extern __shared__ char smem[];
    const uint32_t sb = smem_u32(smem);
    const int tid = threadIdx.x;

    // ---- load W tiles once ----
#pragma unroll
    for (int i = 0; i < 8; i++) {
        int idx = tid + i * 256;
        int r = idx >> 4, c = idx & 15;
        *(uint4*)(smem + SW_HI + r * ROWB + c * 16) =
            *(const uint4*)(Whi + (size_t)r * HD + c * 8);
        *(uint4*)(smem + SW_LO + r * ROWB + c * 16) =
            *(const uint4*)(Wlo + (size_t)r * HD + c * 8);
    }

    const int wid = tid >> 5, lane = tid & 31;
    const int mstrip = wid & 3;
    const int nhalf  = wid >> 2;
    const int lrow = lane & 15, lcol = lane >> 4;

    const uint32_t a0    = sb + SA    + (mstrip * 16 + lrow) * ROWB + lcol * 16;
    const uint32_t w_hi0 = sb + SW_HI + (nhalf * 64 + lrow) * ROWB + lcol * 16;
    const uint32_t w_lo0 = sb + SW_LO + (nhalf * 64 + lrow) * ROWB + lcol * 16;
    const uint4 z4 = make_uint4(0, 0, 0, 0);

    for (int tile = blockIdx.x; tile < ntiles; tile += GEMM_CTAS) {
        const int row0 = tile * 64;

#pragma unroll
        for (int i = 0; i < 4; i++) {
            int idx = tid + i * 256;
            int r = idx >> 4, c = idx & 15;
            int gr = row0 + r;
            uint4 v = z4;
            if (gr < n) {
                if (xf) {
                    const float* srcp = xf + (size_t)gr * HD + c * 8;
                    float4 f0 = *(const float4*)(srcp);
                    float4 f1 = *(const float4*)(srcp + 4);
                    v.x = pack_bf16x2(f0.x, f0.y);
                    v.y = pack_bf16x2(f0.z, f0.w);
                    v.z = pack_bf16x2(f1.x, f1.y);
                    v.w = pack_bf16x2(f1.z, f1.w);
                } else {
                    v = *(const uint4*)(A + (size_t)gr * HD + c * 8);
                }
            }
            *(uint4*)(smem + SA + r * ROWB + c * 16) = v;
        }
        __syncthreads();

        float acc[8][4];
#pragma unroll
        for (int p = 0; p < 8; p++)
#pragma unroll
            for (int j = 0; j < 4; j++) acc[p][j] = 0.0f;

#pragma unroll
        for (int ks = 0; ks < 8; ks++) {
            uint32_t a[4];
            ldm4(a, a0 + ks * 32);
#pragma unroll
            for (int p = 0; p < 4; p++) {
                uint32_t wh[4], wl[4];
                ldm4(wh, w_hi0 + p * (16 * ROWB) + ks * 32);
                mma_bf16(acc[2 * p],     a, wh[0], wh[2]);
                mma_bf16(acc[2 * p + 1], a, wh[1], wh[3]);
                ldm4(wl, w_lo0 + p * (16 * ROWB) + ks * 32);
                mma_bf16(acc[2 * p],     a, wl[0], wl[2]);
                mma_bf16(acc[2 * p + 1], a, wl[1], wl[3]);
            }
        }

        const int rbase = row0 + mstrip * 16 + (lane >> 2);
        const int qc = (lane & 3) * 2;
#pragma unroll
        for (int rr = 0; rr < 2; rr++) {
            int row = rbase + rr * 8;
            if (row < n) {
                float w = rsqrtf((float)cnt[row] + 1.0f);
                __half* dst = M + (size_t)row * HD + nhalf * 64 + qc;
#pragma unroll
                for (int p = 0; p < 8; p++) {
                    __half2 v = __floats2half2_rn(acc[p][rr * 2] * w, acc[p][rr * 2 + 1] * w);
                    *(__half2*)(dst + p * 8) = v;
                }
            }
        }
        __syncthreads();
    }
}

// ---------------- setup1: zero cnt/pooled/counts + weight split --------------
__global__ void setup1(int* __restrict__ cnt, float* __restrict__ pooled,
                       float* __restrict__ counts,
                       const float* __restrict__ W0, const float* __restrict__ W1,
                       const float* __restrict__ W2, const float* __restrict__ W3,
                       __nv_bfloat16* __restrict__ Bhi, __nv_bfloat16* __restrict__ Blo,
                       int n, int G)
{
    int i = blockIdx.x * blockDim.x + threadIdx.x;
    if (i < n) cnt[i] = 0;
    if (i < G * HD) pooled[i] = 0.0f;
    if (i < G) counts[i] = 0.0f;
    if (i < 4 * HD * HD) {
        int l = i >> 14;
        int r = i & (HD * HD - 1);
        const float* W = (l == 0) ? W0 : (l == 1) ? W1 : (l == 2) ? W2 : W3;
        int nn = r >> 7, kk = r & 127;
        float v = W[kk * HD + nn];
        __nv_bfloat16 hi = __float2bfloat16(v);
        __nv_bfloat16 lo = __float2bfloat16(v - __bfloat162float(hi));
        Bhi[i] = hi;
        Blo[i] = lo;
    }
}

// ---------------- setup2: ELL fill + batch histogram --------------------------
__global__ void setup2(const int* __restrict__ src, const int* __restrict__ dst,
                       int* __restrict__ cnt, int* __restrict__ ell,
                       const int* __restrict__ batch, float* __restrict__ counts,
                       int E, int n)
{
    int i = blockIdx.x * blockDim.x + threadIdx.x;
    if (i < E) {
        int d = dst[i];
        int pos = atomicAdd(&cnt[d], 1);
        if (pos < ELLW) ell[(size_t)d * ELLW + pos] = src[i];
    }
    if (i < n) atomicAdd(&counts[batch[i]], 1.0f);
}

// ---------------- fused gather + selfloop + bias + relu (+ pool on last) ----
// R12's exact loop shape; accumulation switched to fp16 HADD2 (2 instrs/edge).
__global__ __launch_bounds__(256) void gather_nodes(
    const __half* __restrict__ m, const int* __restrict__ ell,
    const int* __restrict__ cnt, const float* __restrict__ bias,
    __nv_bfloat16* __restrict__ out_h,
    const int* __restrict__ batch, float* __restrict__ pooled,
    int mode, int n)
{
    int d = blockIdx.x * (blockDim.x >> 5) + (threadIdx.x >> 5);
    if (d >= n) return;
    const int lane = threadIdx.x & 31;
    const int c4 = lane << 2;

    // self term -> fp16 accumulators
    uint2 sraw = *(const uint2*)(m + (size_t)d * HD + c4);
    __half2 c0 = *(const __half2*)&sraw.x;
    __half2 c1 = *(const __half2*)&sraw.y;

    const int deg = cnt[d];
    const int* row = ell + (size_t)d * ELLW;

    for (int base = 0; base < deg; base += 32) {
        int idx = (base + lane < deg) ? __ldg(row + base + lane) : 0;
        int lim = min(32, deg - base);
#pragma unroll 8
        for (int j = 0; j < lim; j++) {
            int s = __shfl_sync(0xffffffffu, idx, j);
            uint2 raw = *(const uint2*)(m + (size_t)s * HD + c4);
            c0 = __hadd2(c0, *(const __half2*)&raw.x);
            c1 = __hadd2(c1, *(const __half2*)&raw.y);
        }
    }

    float2 f0 = __half22float2(c0);
    float2 f1 = __half22float2(c1);
    float a0 = f0.x, a1 = f0.y, a2 = f1.x, a3 = f1.y;

    float w = rsqrtf((float)deg + 1.0f);
    float4 bb = *(const float4*)(bias + c4);
    float o0 = fmaxf(fmaf(a0, w, bb.x), 0.f);
    float o1 = fmaxf(fmaf(a1, w, bb.y), 0.f);
    float o2 = fmaxf(fmaf(a2, w, bb.z), 0.f);
    float o3 = fmaxf(fmaf(a3, w, bb.w), 0.f);

    if (mode == 0) {
        __nv_bfloat162 h0 = {__float2bfloat16(o0), __float2bfloat16(o1)};
        __nv_bfloat162 h1 = {__float2bfloat16(o2), __float2bfloat16(o3)};
        *(__nv_bfloat162*)(out_h + (size_t)d * HD + c4)     = h0;
        *(__nv_bfloat162*)(out_h + (size_t)d * HD + c4 + 2) = h1;
    } else {
        int g = batch[d];
        float* p = pooled + (size_t)g * HD + c4;
        asm volatile("red.global.add.v4.f32 [%0], {%1, %2, %3, %4};"
                     :: "l"(p), "f"(o0), "f"(o1), "f"(o2), "f"(o3) : "memory");
    }
}

// ---------------- final linear head --------------------------------------------
__global__ void final_linear(const float* __restrict__ pooled, const float* __restrict__ counts,
                             const float* __restrict__ linW, const float* __restrict__ linb,
                             float* __restrict__ out)
{
    int g = blockIdx.x;
    int c = threadIdx.x;
    float cntv = fmaxf(counts[g], 1.0f);
    float p = pooled[g * HD + c] / cntv;
    float v0 = p * linW[c * 2 + 0];
    float v1 = p * linW[c * 2 + 1];
#pragma unroll
    for (int o = 16; o > 0; o >>= 1) {
        v0 += __shfl_xor_sync(0xffffffffu, v0, o);
        v1 += __shfl_xor_sync(0xffffffffu, v1, o);
    }
    __shared__ float s0[4], s1[4];
    int w = threadIdx.x >> 5;
    if ((threadIdx.x & 31) == 0) { s0[w] = v0; s1[w] = v1; }
    __syncthreads();
    if (threadIdx.x == 0) {
        out[g * 2 + 0] = s0[0] + s0[1] + s0[2] + s0[3] + linb[0];
        out[g * 2 + 1] = s1[0] + s1[1] + s1[2] + s1[3] + linb[1];
    }
}

// ---------------- launch ---------------------------------------------------------
extern "C" void kernel_launch(void* const* d_in, const int* in_sizes, int n_in,
                              void* d_out, int out_size)
{
    const float* x     = (const float*)d_in[0];
    const int*   ei    = (const int*)d_in[1];
    const int*   batch = (const int*)d_in[2];
    const float* W[4]  = {(const float*)d_in[3], (const float*)d_in[5],
                          (const float*)d_in[7], (const float*)d_in[9]};
    const float* bv[4] = {(const float*)d_in[4], (const float*)d_in[6],
                          (const float*)d_in[8], (const float*)d_in[10]};
    const float* linW  = (const float*)d_in[11];
    const float* linb  = (const float*)d_in[12];
    float* out = (float*)d_out;

    const int n = in_sizes[0] / HD;
    const int E = in_sizes[1] / 2;
    const int G = out_size / 2;
    const int* src = ei;
    const int* dst = ei + E;

    float *pooled, *counts;
    __half* msg;
    int *ell, *cnt;
    __nv_bfloat16 *hbuf, *whi, *wlo;
    cudaGetSymbolAddress((void**)&msg,    g_msg);
    cudaGetSymbolAddress((void**)&hbuf,   g_h);
    cudaGetSymbolAddress((void**)&whi,    g_whi);
    cudaGetSymbolAddress((void**)&wlo,    g_wlo);
    cudaGetSymbolAddress((void**)&ell,    g_ell);
    cudaGetSymbolAddress((void**)&cnt,    g_cnt);
    cudaGetSymbolAddress((void**)&pooled, g_pooled);
    cudaGetSymbolAddress((void**)&counts, g_counts);

    cudaFuncSetAttribute(gemm_hmma, cudaFuncAttributeMaxDynamicSharedMemorySize, S_TOT);

    // setup (2 launches)
    int s1n = n;
    if (G * HD > s1n) s1n = G * HD;
    if (4 * HD * HD > s1n) s1n = 4 * HD * HD;
    setup1<<<(s1n + 255) / 256, 256>>>(cnt, pooled, counts,
                                       W[0], W[1], W[2], W[3], whi, wlo, n, G);
    int s2n = (E > n) ? E : n;
    setup2<<<(s2n + 255) / 256, 256>>>(src, dst, cnt, ell, batch, counts, E, n);

    const int ntiles = (n + 63) / 64;
    for (int l = 0; l < 4; l++) {
        gemm_hmma<<<GEMM_CTAS, 256, S_TOT>>>(hbuf, (l == 0) ? x : nullptr,
                                             whi + l * HD * HD, wlo + l * HD * HD,
                                             cnt, msg, n, ntiles);
        gather_nodes<<<(n + 7) / 8, 256>>>(msg, ell, cnt, bv[l],
                                           hbuf, batch, pooled, (l == 3) ? 1 : 0, n);
    }

    final_linear<<<G, 128>>>(pooled, counts, linW, linb, out);
}

// round 17
// speedup vs baseline: 1.3819x; 1.3819x over previous
#include <cuda_runtime.h>
#include <cuda_bf16.h>
#include <cuda_fp16.h>
#include <cstdint>
#include <cstddef>

#define HD   128
#define NMAX 100000
#define GMAX 1024
#define ELLW 64

// ---------------- scratch (device globals; no allocation allowed) ----------
__device__ __align__(256) __half g_msg[NMAX * HD];            // m' fp16 = (h @ W) * dinv[row]
__device__ __align__(256) __nv_bfloat16 g_h[NMAX * HD];       // h bf16 (GEMM A input)
__device__ __align__(256) __nv_bfloat16 g_whi[4 * HD * HD];   // W^T split hi ([N,K] row-major)
__device__ __align__(256) __nv_bfloat16 g_wlo[4 * HD * HD];   // W^T split lo
__device__ __align__(256) int   g_ell[NMAX * ELLW];
__device__ __align__(256) int   g_cnt[NMAX];
__device__ __align__(256) float g_pooled[GMAX * HD];
__device__ __align__(256) float g_counts[GMAX];

// ---------------- helpers ----------------------------------------------------
__device__ __forceinline__ uint32_t smem_u32(const void* p) {
    uint32_t a;
    asm("{ .reg .u64 t; cvta.to.shared.u64 t, %1; cvt.u32.u64 %0, t; }" : "=r"(a) : "l"(p));
    return a;
}

__device__ __forceinline__ void ldm4(uint32_t* r, uint32_t addr) {
    asm volatile("ldmatrix.sync.aligned.m8n8.x4.shared.b16 {%0,%1,%2,%3}, [%4];"
                 : "=r"(r[0]), "=r"(r[1]), "=r"(r[2]), "=r"(r[3]) : "r"(addr));
}

__device__ __forceinline__ void mma_bf16(float* c, const uint32_t* a,
                                         uint32_t b0, uint32_t b1) {
    asm volatile(
        "mma.sync.aligned.m16n8k16.row.col.f32.bf16.bf16.f32 "
        "{%0,%1,%2,%3}, {%4,%5,%6,%7}, {%8,%9}, {%0,%1,%2,%3};"
        : "+f"(c[0]), "+f"(c[1]), "+f"(c[2]), "+f"(c[3])
        : "r"(a[0]), "r"(a[1]), "r"(a[2]), "r"(a[3]), "r"(b0), "r"(b1));
}

__device__ __forceinline__ uint32_t pack_bf16x2(float x, float y) {
    __nv_bfloat162 b = {__float2bfloat16(x), __float2bfloat16(y)};
    return *(uint32_t*)&b;
}

// SMEM plan: padded rows, stride 136 bf16 = 272 bytes (conflict-free ldmatrix)
#define ROWB 272
#define SA    0
#define SW_HI (SA + 64 * ROWB)
#define SW_LO (SW_HI + 128 * ROWB)
#define S_TOT (SW_LO + 128 * ROWB)

#define GEMM_CTAS 296   // 2 per SM, persistent

// ---------------- persistent HMMA GEMM (2-pass bf16) [exact R12] -------------
__global__ __launch_bounds__(256, 2) void gemm_hmma(
    const __nv_bfloat16* __restrict__ A, const float* __restrict__ xf,
    const __nv_bfloat16* __restrict__ Whi, const __nv_bfloat16* __restrict__ Wlo,
    const int* __restrict__ cnt, __half* __restrict__ M, int n, int ntiles)
{
    extern __shared__ char smem[];
    const uint32_t sb = smem_u32(smem);
    const int tid = threadIdx.x;

    // ---- load W tiles once ----
#pragma unroll
    for (int i = 0; i < 8; i++) {
        int idx = tid + i * 256;
        int r = idx >> 4, c = idx & 15;
        *(uint4*)(smem + SW_HI + r * ROWB + c * 16) =
            *(const uint4*)(Whi + (size_t)r * HD + c * 8);
        *(uint4*)(smem + SW_LO + r * ROWB + c * 16) =
            *(const uint4*)(Wlo + (size_t)r * HD + c * 8);
    }

    const int wid = tid >> 5, lane = tid & 31;
    const int mstrip = wid & 3;
    const int nhalf  = wid >> 2;
    const int lrow = lane & 15, lcol = lane >> 4;

    const uint32_t a0    = sb + SA    + (mstrip * 16 + lrow) * ROWB + lcol * 16;
    const uint32_t w_hi0 = sb + SW_HI + (nhalf * 64 + lrow) * ROWB + lcol * 16;
    const uint32_t w_lo0 = sb + SW_LO + (nhalf * 64 + lrow) * ROWB + lcol * 16;
    const uint4 z4 = make_uint4(0, 0, 0, 0);

    for (int tile = blockIdx.x; tile < ntiles; tile += GEMM_CTAS) {
        const int row0 = tile * 64;

#pragma unroll
        for (int i = 0; i < 4; i++) {
            int idx = tid + i * 256;
            int r = idx >> 4, c = idx & 15;
            int gr = row0 + r;
            uint4 v = z4;
            if (gr < n) {
                if (xf) {
                    const float* srcp = xf + (size_t)gr * HD + c * 8;
                    float4 f0 = *(const float4*)(srcp);
                    float4 f1 = *(const float4*)(srcp + 4);
                    v.x = pack_bf16x2(f0.x, f0.y);
                    v.y = pack_bf16x2(f0.z, f0.w);
                    v.z = pack_bf16x2(f1.x, f1.y);
                    v.w = pack_bf16x2(f1.z, f1.w);
                } else {
                    v = *(const uint4*)(A + (size_t)gr * HD + c * 8);
                }
            }
            *(uint4*)(smem + SA + r * ROWB + c * 16) = v;
        }
        __syncthreads();

        float acc[8][4];
#pragma unroll
        for (int p = 0; p < 8; p++)
#pragma unroll
            for (int j = 0; j < 4; j++) acc[p][j] = 0.0f;

#pragma unroll
        for (int ks = 0; ks < 8; ks++) {
            uint32_t a[4];
            ldm4(a, a0 + ks * 32);
#pragma unroll
            for (int p = 0; p < 4; p++) {
                uint32_t wh[4], wl[4];
                ldm4(wh, w_hi0 + p * (16 * ROWB) + ks * 32);
                mma_bf16(acc[2 * p],     a, wh[0], wh[2]);
                mma_bf16(acc[2 * p + 1], a, wh[1], wh[3]);
                ldm4(wl, w_lo0 + p * (16 * ROWB) + ks * 32);
                mma_bf16(acc[2 * p],     a, wl[0], wl[2]);
                mma_bf16(acc[2 * p + 1], a, wl[1], wl[3]);
            }
        }

        const int rbase = row0 + mstrip * 16 + (lane >> 2);
        const int qc = (lane & 3) * 2;
#pragma unroll
        for (int rr = 0; rr < 2; rr++) {
            int row = rbase + rr * 8;
            if (row < n) {
                float w = rsqrtf((float)cnt[row] + 1.0f);
                __half* dst = M + (size_t)row * HD + nhalf * 64 + qc;
#pragma unroll
                for (int p = 0; p < 8; p++) {
                    __half2 v = __floats2half2_rn(acc[p][rr * 2] * w, acc[p][rr * 2 + 1] * w);
                    *(__half2*)(dst + p * 8) = v;
                }
            }
        }
        __syncthreads();
    }
}

// ---------------- setup1: zero cnt/pooled/counts + weight split --------------
__global__ void setup1(int* __restrict__ cnt, float* __restrict__ pooled,
                       float* __restrict__ counts,
                       const float* __restrict__ W0, const float* __restrict__ W1,
                       const float* __restrict__ W2, const float* __restrict__ W3,
                       __nv_bfloat16* __restrict__ Bhi, __nv_bfloat16* __restrict__ Blo,
                       int n, int G)
{
    int i = blockIdx.x * blockDim.x + threadIdx.x;
    if (i < n) cnt[i] = 0;
    if (i < G * HD) pooled[i] = 0.0f;
    if (i < G) counts[i] = 0.0f;
    if (i < 4 * HD * HD) {
        int l = i >> 14;
        int r = i & (HD * HD - 1);
        const float* W = (l == 0) ? W0 : (l == 1) ? W1 : (l == 2) ? W2 : W3;
        int nn = r >> 7, kk = r & 127;
        float v = W[kk * HD + nn];
        __nv_bfloat16 hi = __float2bfloat16(v);
        __nv_bfloat16 lo = __float2bfloat16(v - __bfloat162float(hi));
        Bhi[i] = hi;
        Blo[i] = lo;
    }
}

// ---------------- setup2: ELL fill + batch histogram --------------------------
__global__ void setup2(const int* __restrict__ src, const int* __restrict__ dst,
                       int* __restrict__ cnt, int* __restrict__ ell,
                       const int* __restrict__ batch, float* __restrict__ counts,
                       int E, int n)
{
    int i = blockIdx.x * blockDim.x + threadIdx.x;
    if (i < E) {
        int d = dst[i];
        int pos = atomicAdd(&cnt[d], 1);
        if (pos < ELLW) ell[(size_t)d * ELLW + pos] = src[i];
    }
    if (i < n) atomicAdd(&counts[batch[i]], 1.0f);
}

// ---------------- fused gather + selfloop + bias + relu (+ pool on last) ----
// [exact R12 structure: warp/node, 8B lanes, f32 accumulate, unroll 8]
// micro-trim: mode-0 output coalesced into a single 8B store.
__global__ __launch_bounds__(256) void gather_nodes(
    const __half* __restrict__ m, const int* __restrict__ ell,
    const int* __restrict__ cnt, const float* __restrict__ bias,
    __nv_bfloat16* __restrict__ out_h,
    const int* __restrict__ batch, float* __restrict__ pooled,
    int mode, int n)
{
    int d = blockIdx.x * (blockDim.x >> 5) + (threadIdx.x >> 5);
    if (d >= n) return;
    const int lane = threadIdx.x & 31;
    const int c4 = lane << 2;

    // self term
    uint2 sraw = *(const uint2*)(m + (size_t)d * HD + c4);
    float2 s0 = __half22float2(*(const __half2*)&sraw.x);
    float2 s1 = __half22float2(*(const __half2*)&sraw.y);
    float a0 = s0.x, a1 = s0.y, a2 = s1.x, a3 = s1.y;

    const int deg = cnt[d];
    const int* row = ell + (size_t)d * ELLW;

    for (int base = 0; base < deg; base += 32) {
        int idx = (base + lane < deg) ? __ldg(row + base + lane) : 0;
        int lim = min(32, deg - base);
#pragma unroll 8
        for (int j = 0; j < lim; j++) {
            int s = __shfl_sync(0xffffffffu, idx, j);
            uint2 raw = *(const uint2*)(m + (size_t)s * HD + c4);
            float2 v0 = __half22float2(*(const __half2*)&raw.x);
            float2 v1 = __half22float2(*(const __half2*)&raw.y);
            a0 += v0.x; a1 += v0.y; a2 += v1.x; a3 += v1.y;
        }
    }

    float w = rsqrtf((float)deg + 1.0f);
    float4 bb = *(const float4*)(bias + c4);
    float o0 = fmaxf(fmaf(a0, w, bb.x), 0.f);
    float o1 = fmaxf(fmaf(a1, w, bb.y), 0.f);
    float o2 = fmaxf(fmaf(a2, w, bb.z), 0.f);
    float o3 = fmaxf(fmaf(a3, w, bb.w), 0.f);

    if (mode == 0) {
        uint2 hv;
        hv.x = pack_bf16x2(o0, o1);
        hv.y = pack_bf16x2(o2, o3);
        *(uint2*)(out_h + (size_t)d * HD + c4) = hv;   // single 8B store
    } else {
        int g = batch[d];
        float* p = pooled + (size_t)g * HD + c4;
        asm volatile("red.global.add.v4.f32 [%0], {%1, %2, %3, %4};"
                     :: "l"(p), "f"(o0), "f"(o1), "f"(o2), "f"(o3) : "memory");
    }
}

// ---------------- final linear head --------------------------------------------
__global__ void final_linear(const float* __restrict__ pooled, const float* __restrict__ counts,
                             const float* __restrict__ linW, const float* __restrict__ linb,
                             float* __restrict__ out)
{
    int g = blockIdx.x;
    int c = threadIdx.x;
    float cntv = fmaxf(counts[g], 1.0f);
    float p = pooled[g * HD + c] / cntv;
    float v0 = p * linW[c * 2 + 0];
    float v1 = p * linW[c * 2 + 1];
#pragma unroll
    for (int o = 16; o > 0; o >>= 1) {
        v0 += __shfl_xor_sync(0xffffffffu, v0, o);
        v1 += __shfl_xor_sync(0xffffffffu, v1, o);
    }
    __shared__ float s0[4], s1[4];
    int w = threadIdx.x >> 5;
    if ((threadIdx.x & 31) == 0) { s0[w] = v0; s1[w] = v1; }
    __syncthreads();
    if (threadIdx.x == 0) {
        out[g * 2 + 0] = s0[0] + s0[1] + s0[2] + s0[3] + linb[0];
        out[g * 2 + 1] = s1[0] + s1[1] + s1[2] + s1[3] + linb[1];
    }
}

// ---------------- launch ---------------------------------------------------------
extern "C" void kernel_launch(void* const* d_in, const int* in_sizes, int n_in,
                              void* d_out, int out_size)
{
    const float* x     = (const float*)d_in[0];
    const int*   ei    = (const int*)d_in[1];
    const int*   batch = (const int*)d_in[2];
    const float* W[4]  = {(const float*)d_in[3], (const float*)d_in[5],
                          (const float*)d_in[7], (const float*)d_in[9]};
    const float* bv[4] = {(const float*)d_in[4], (const float*)d_in[6],
                          (const float*)d_in[8], (const float*)d_in[10]};
    const float* linW  = (const float*)d_in[11];
    const float* linb  = (const float*)d_in[12];
    float* out = (float*)d_out;

    const int n = in_sizes[0] / HD;
    const int E = in_sizes[1] / 2;
    const int G = out_size / 2;
    const int* src = ei;
    const int* dst = ei + E;

    float *pooled, *counts;
    __half* msg;
    int *ell, *cnt;
    __nv_bfloat16 *hbuf, *whi, *wlo;
    cudaGetSymbolAddress((void**)&msg,    g_msg);
    cudaGetSymbolAddress((void**)&hbuf,   g_h);
    cudaGetSymbolAddress((void**)&whi,    g_whi);
    cudaGetSymbolAddress((void**)&wlo,    g_wlo);
    cudaGetSymbolAddress((void**)&ell,    g_ell);
    cudaGetSymbolAddress((void**)&cnt,    g_cnt);
    cudaGetSymbolAddress((void**)&pooled, g_pooled);
    cudaGetSymbolAddress((void**)&counts, g_counts);

    cudaFuncSetAttribute(gemm_hmma, cudaFuncAttributeMaxDynamicSharedMemorySize, S_TOT);

    // setup (2 launches)
    int s1n = n;
    if (G * HD > s1n) s1n = G * HD;
    if (4 * HD * HD > s1n) s1n = 4 * HD * HD;
    setup1<<<(s1n + 255) / 256, 256>>>(cnt, pooled, counts,
                                       W[0], W[1], W[2], W[3], whi, wlo, n, G);
    int s2n = (E > n) ? E : n;
    setup2<<<(s2n + 255) / 256, 256>>>(src, dst, cnt, ell, batch, counts, E, n);

    const int ntiles = (n + 63) / 64;
    for (int l = 0; l < 4; l++) {
        gemm_hmma<<<GEMM_CTAS, 256, S_TOT>>>(hbuf, (l == 0) ? x : nullptr,
                                             whi + l * HD * HD, wlo + l * HD * HD,
                                             cnt, msg, n, ntiles);
        gather_nodes<<<(n + 7) / 8, 256>>>(msg, ell, cnt, bv[l],
                                           hbuf, batch, pooled, (l == 3) ? 1 : 0, n);
    }

    final_linear<<<G, 128>>>(pooled, counts, linW, linb, out);
}